// round 4
// baseline (speedup 1.0000x reference)
#include <cuda_runtime.h>
#include <cub/cub.cuh>

// Problem constants
#define NB_   80000      // B*N nodes layer 0/1
#define BGR_  8          // graphs
#define NPG_  10000      // nodes per graph (layer 1)
#define EDG_  640000     // edges
#define CC_   128        // channels
#define FF_   64         // input features
#define KK1_  6000       // kept after pool1 (per graph)
#define NB1_  48000      // B*KK1
#define KK2_  3600       // kept after pool2 (per graph)
#define NB2_  28800      // B*KK2

#define INVALID_KEY 0x000FFFFF   // sorts after any node id (20-bit sort)

// ---------------- static device scratch (no allocs allowed) ----------------
__device__ float g_bufA[NB_ * CC_];
__device__ float g_bufB[NB_ * CC_];
__device__ float g_bufC[NB_ * CC_];
__device__ float g_scores[NB_];
__device__ float g_skey[NB_];
__device__ int   g_iota[NB_];
__device__ int   g_sidx[NB_];
__device__ int   g_newid[NB_];
__device__ int   g_src2[EDG_];
__device__ int   g_dst2[EDG_];
__device__ unsigned char g_mask2[EDG_];
__device__ int   g_offs[9];
__device__ float g_out1[BGR_ * CC_];
__device__ float g_out2[BGR_ * CC_];
__device__ int   g_keys[EDG_];
__device__ int   g_keysB[EDG_];
__device__ int   g_vals[EDG_];
__device__ int   g_valsB[EDG_];
__device__ int   g_counts[NB_];
__device__ int   g_rowptr[NB_ + 1];
__device__ unsigned char g_cubtmp[1u << 25];  // 32 MB cub temp

// ---------------- XLA-GPU (MLIR math polynomial approximation) tanh -------
// Matches mlir/lib/Dialect/Math/Transforms/PolynomialApproximation.cpp:
// clamp to +-7.99881172180175781, |x|<0.0004 -> x, fused-FMA rational.
__device__ __forceinline__ float xla_tanh(float ax) {
    const float plus_clamp  = 7.99881172180175781f;
    const float minus_clamp = -7.99881172180175781f;
    const float tiny = 0.0004f;
    const float alpha_1  = 4.89352455891786e-03f;
    const float alpha_3  = 6.37261928875436e-04f;
    const float alpha_5  = 1.48572235717979e-05f;
    const float alpha_7  = 5.12229709037114e-08f;
    const float alpha_9  = -8.60467152213735e-11f;
    const float alpha_11 = 2.00018790482477e-13f;
    const float alpha_13 = -2.76076847742355e-16f;
    const float beta_0 = 4.89352518554385e-03f;
    const float beta_2 = 2.26843463243900e-03f;
    const float beta_4 = 1.18534705686654e-04f;
    const float beta_6 = 1.19825839466702e-06f;

    float x = fminf(fmaxf(ax, minus_clamp), plus_clamp);
    float x2 = x * x;
    float p = fmaf(x2, alpha_13, alpha_11);
    p = fmaf(x2, p, alpha_9);
    p = fmaf(x2, p, alpha_7);
    p = fmaf(x2, p, alpha_5);
    p = fmaf(x2, p, alpha_3);
    p = fmaf(x2, p, alpha_1);
    p = x * p;
    float q = fmaf(x2, beta_6, beta_4);
    q = fmaf(x2, q, beta_2);
    q = fmaf(x2, q, beta_0);
    float r = p / q;
    return (fabsf(ax) < tiny) ? ax : r;
}

// ---------------- GEMM: [M x K] @ [K x 128] + bias (+relu) ----------------
// k-sequential FMA accumulation (matches cublas/Eigen order).
template <int K, bool RELU>
__global__ void __launch_bounds__(256) gemm_kernel(const float* __restrict__ A,
                                                   const float* __restrict__ W,
                                                   const float* __restrict__ bias,
                                                   float* __restrict__ out) {
    __shared__ float As[64][36];
    __shared__ float Bs[32][128];

    const int tid  = threadIdx.x;
    const int row0 = blockIdx.x * 64;
    const int warp = tid >> 5, lane = tid & 31;
    const int r0 = warp * 8;
    const int c0 = lane * 4;

    float acc[8][4];
#pragma unroll
    for (int i = 0; i < 8; i++)
#pragma unroll
        for (int j = 0; j < 4; j++) acc[i][j] = 0.f;

    for (int k0 = 0; k0 < K; k0 += 32) {
        {
            const int r  = tid >> 3;
            const int k4 = (tid & 7) * 4;
            float4 v0 = *(const float4*)(A + (size_t)(row0 + r) * K + k0 + k4);
            float4 v1 = *(const float4*)(A + (size_t)(row0 + r + 32) * K + k0 + k4);
            *(float4*)&As[r][k4]      = v0;
            *(float4*)&As[r + 32][k4] = v1;
        }
#pragma unroll
        for (int it = 0; it < 4; ++it) {
            const int f  = tid + it * 256;
            const int k  = f >> 5;
            const int c4 = (f & 31) * 4;
            *(float4*)&Bs[k][c4] = *(const float4*)(W + (size_t)(k0 + k) * 128 + c4);
        }
        __syncthreads();
#pragma unroll
        for (int kk = 0; kk < 32; ++kk) {
            const float4 b = *(const float4*)&Bs[kk][c0];
#pragma unroll
            for (int i = 0; i < 8; i++) {
                const float a = As[r0 + i][kk];
                acc[i][0] = fmaf(a, b.x, acc[i][0]);
                acc[i][1] = fmaf(a, b.y, acc[i][1]);
                acc[i][2] = fmaf(a, b.z, acc[i][2]);
                acc[i][3] = fmaf(a, b.w, acc[i][3]);
            }
        }
        __syncthreads();
    }

    const float4 bv = *(const float4*)(bias + c0);
#pragma unroll
    for (int i = 0; i < 8; i++) {
        float4 o;
        o.x = acc[i][0] + bv.x;
        o.y = acc[i][1] + bv.y;
        o.z = acc[i][2] + bv.z;
        o.w = acc[i][3] + bv.w;
        if (RELU) {
            o.x = fmaxf(o.x, 0.f); o.y = fmaxf(o.y, 0.f);
            o.z = fmaxf(o.z, 0.f); o.w = fmaxf(o.w, 0.f);
        }
        *(float4*)(out + (size_t)(row0 + r0 + i) * 128 + c0) = o;
    }
}

// ---------------- CSR build helpers ----------------
__global__ void fill0_kernel(int* a, int n) {
    int i = blockIdx.x * blockDim.x + threadIdx.x;
    if (i < n) a[i] = 0;
}
__global__ void build_keys_kernel(const int* __restrict__ dst, const int* __restrict__ src,
                                  const unsigned char* __restrict__ mask,
                                  int* __restrict__ keys, int* __restrict__ vals,
                                  int* __restrict__ counts, int nE) {
    int e = blockIdx.x * blockDim.x + threadIdx.x;
    if (e >= nE) return;
    const bool valid = mask ? (mask[e] != 0) : true;
    keys[e] = valid ? dst[e] : INVALID_KEY;
    vals[e] = src[e];
    if (valid) atomicAdd(&counts[dst[e]], 1);
}
__global__ void set_last_kernel(int* rowptr, const int* counts, int n) {
    if (threadIdx.x == 0) rowptr[n] = rowptr[n - 1] + counts[n - 1];
}

// ---------------- deterministic aggregation (warp per node) ----------------
template <bool ADD_SELF>
__global__ void agg_kernel(const float* __restrict__ x,
                           const int* __restrict__ rowptr,
                           const int* __restrict__ srcs,
                           float* __restrict__ out, int n) {
    const int node = blockIdx.x * 8 + (threadIdx.x >> 5);
    if (node >= n) return;
    const int lane = threadIdx.x & 31;
    const int b = rowptr[node], e = rowptr[node + 1];
    float4 acc = make_float4(0.f, 0.f, 0.f, 0.f);
    for (int i = b; i < e; ++i) {
        const int s = srcs[i];
        const float4 v = *(const float4*)(x + (size_t)s * CC_ + lane * 4);
        acc.x += v.x; acc.y += v.y; acc.z += v.z; acc.w += v.w;
    }
    if (ADD_SELF) {
        const float4 xv = *(const float4*)(x + (size_t)node * CC_ + lane * 4);
        acc.x = xv.x + acc.x; acc.y = xv.y + acc.y;
        acc.z = xv.z + acc.z; acc.w = xv.w + acc.w;
    }
    *(float4*)(out + (size_t)node * CC_ + lane * 4) = acc;
}

// ---------------- SAGPool score, sequential dots (thread per node) --------
__global__ void score_kernel(const float* __restrict__ agg, const float* __restrict__ x,
                             const float* __restrict__ Wrel, const float* __restrict__ brel,
                             const float* __restrict__ Wroot,
                             float* __restrict__ scores, int n) {
    const int node = blockIdx.x * blockDim.x + threadIdx.x;
    if (node >= n) return;
    const float* a  = agg + (size_t)node * CC_;
    const float* xx = x + (size_t)node * CC_;
    float t1 = 0.f;
#pragma unroll 16
    for (int c = 0; c < CC_; ++c) t1 = fmaf(a[c], Wrel[c], t1);
    t1 = t1 + brel[0];
    float t2 = 0.f;
#pragma unroll 16
    for (int c = 0; c < CC_; ++c) t2 = fmaf(xx[c], Wroot[c], t2);
    scores[node] = xla_tanh(t1 + t2);
}

// ---------------- small helpers ----------------
__global__ void iota_kernel(int* a, int n) {
    int i = blockIdx.x * blockDim.x + threadIdx.x;
    if (i < n) a[i] = i;
}
__global__ void filln1_kernel(int* a, int n) {
    int i = blockIdx.x * blockDim.x + threadIdx.x;
    if (i < n) a[i] = -1;
}
__global__ void offs_kernel(int* offs, int npg) {
    int t = threadIdx.x;
    if (t < 9) offs[t] = t * npg;
}

// ---------------- selection/gather after sort (1 warp / kept node) -------
__global__ void select_kernel(const float* __restrict__ skey, const int* __restrict__ sidx,
                              const float* __restrict__ xin, float* __restrict__ xout,
                              int* __restrict__ newid, int npg, int k) {
    const int j = blockIdx.x * 8 + (threadIdx.x >> 5);
    if (j >= BGR_ * k) return;
    const int g = j / k, jj = j - g * k;
    const int srcpos = g * npg + jj;
    const int orig = sidx[srcpos];
    const float val = skey[srcpos];
    const int lane = threadIdx.x & 31;
    float4 v = *(const float4*)(xin + (size_t)orig * CC_ + lane * 4);
    v.x *= val; v.y *= val; v.z *= val; v.w *= val;
    *(float4*)(xout + (size_t)j * CC_ + lane * 4) = v;
    if (lane == 0) newid[orig] = j;
}

// ---------------- edge remap after pooling ----------------
__global__ void remap_kernel(const int* __restrict__ src, const int* __restrict__ dst,
                             const int* __restrict__ newid,
                             int* __restrict__ src2, int* __restrict__ dst2,
                             unsigned char* __restrict__ mask2) {
    const int e = blockIdx.x * blockDim.x + threadIdx.x;
    if (e >= EDG_) return;
    const int s = newid[src[e]];
    const int d = newid[dst[e]];
    const bool ok = (s >= 0) && (d >= 0);
    src2[e] = s; dst2[e] = d; mask2[e] = ok ? 1 : 0;
}

// ---------------- per-graph mean pooling ----------------
__global__ void mean_kernel(const float* __restrict__ x, float* __restrict__ out, int k) {
    __shared__ float col[CC_];
    const int b = blockIdx.x, tid = threadIdx.x;
    if (tid < CC_) col[tid] = 0.f;
    __syncthreads();
    float s = 0.f;
    const float* base = x + (size_t)b * k * CC_;
    const int total = k * CC_;
    for (int idx = tid; idx < total; idx += 256) s += base[idx];
    atomicAdd(&col[tid & 127], s);
    __syncthreads();
    if (tid < CC_) out[b * CC_ + tid] = col[tid] / (float)k;
}

// ---------------- final MLP head (single block) ----------------
__global__ void head_kernel(const float* __restrict__ out1, const float* __restrict__ out2,
                            const float* __restrict__ Wg, const float* __restrict__ bg,
                            const float* __restrict__ Wr1, const float* __restrict__ br1,
                            const float* __restrict__ gg1, const float* __restrict__ be1,
                            const float* __restrict__ Wr2, const float* __restrict__ br2,
                            const float* __restrict__ gg2, const float* __restrict__ be2,
                            const float* __restrict__ Wout, float* __restrict__ out) {
    __shared__ float cat[8][256];
    __shared__ float gmat[8][128];
    __shared__ float r1[8][64];
    __shared__ float r2[8][32];
    const int tid = threadIdx.x;  // 256 threads
    for (int i = tid; i < 8 * 128; i += 256) {
        const int b = i >> 7, c = i & 127;
        cat[b][c]       = out1[i];
        cat[b][c + 128] = out2[i];
    }
    __syncthreads();
    const float inv = 1.0f / sqrtf(1.0f + 1e-5f);
    if (tid < 128) {
        for (int b = 0; b < 8; b++) {
            float s = 0.f;
            for (int k = 0; k < 256; k++) s = fmaf(cat[b][k], Wg[k * 128 + tid], s);
            gmat[b][tid] = s + bg[tid];
        }
    }
    __syncthreads();
    if (tid < 64) {
        for (int b = 0; b < 8; b++) {
            float s = 0.f;
            for (int k = 0; k < 128; k++) s = fmaf(gmat[b][k], Wr1[k * 64 + tid], s);
            s = (s + br1[tid]) * inv * gg1[tid] + be1[tid];
            r1[b][tid] = fmaxf(s, 0.f);
        }
    }
    __syncthreads();
    if (tid < 32) {
        for (int b = 0; b < 8; b++) {
            float s = 0.f;
            for (int k = 0; k < 64; k++) s = fmaf(r1[b][k], Wr2[k * 32 + tid], s);
            s = (s + br2[tid]) * inv * gg2[tid] + be2[tid];
            r2[b][tid] = fmaxf(s, 0.f);
        }
    }
    __syncthreads();
    if (tid < 32) {
        const int b = tid >> 2, j = tid & 3;
        float s = 0.f;
        for (int k = 0; k < 32; k++) s = fmaf(r2[b][k], Wout[k * 4 + j], s);
        out[b * 4 + j] = s;
    }
}

// ---------------- host orchestration ----------------
static void build_csr(const int* dst, const int* src, const unsigned char* mask,
                      int* keys, int* keysB, int* vals, int* valsB,
                      int* counts, int* rowptr, unsigned char* cubtmp, int n_nodes) {
    fill0_kernel<<<(n_nodes + 255) / 256, 256>>>(counts, n_nodes);
    build_keys_kernel<<<EDG_ / 256, 256>>>(dst, src, mask, keys, vals, counts, EDG_);
    size_t tmp = 0;
    cub::DeviceScan::ExclusiveSum(nullptr, tmp, counts, rowptr, n_nodes);
    if (tmp > sizeof(g_cubtmp)) tmp = sizeof(g_cubtmp);
    cub::DeviceScan::ExclusiveSum((void*)cubtmp, tmp, counts, rowptr, n_nodes);
    set_last_kernel<<<1, 32>>>(rowptr, counts, n_nodes);
    size_t tmp2 = 0;
    cub::DeviceRadixSort::SortPairs(nullptr, tmp2, keys, keysB, vals, valsB, EDG_, 0, 20);
    if (tmp2 > sizeof(g_cubtmp)) tmp2 = sizeof(g_cubtmp);
    cub::DeviceRadixSort::SortPairs((void*)cubtmp, tmp2, keys, keysB, vals, valsB, EDG_, 0, 20);
}

extern "C" void kernel_launch(void* const* d_in, const int* in_sizes, int n_in,
                              void* d_out, int out_size) {
    const float* x    = (const float*)d_in[0];
    const int*   ei   = (const int*)d_in[1];
    const int*   src  = ei;
    const int*   dst  = ei + EDG_;
    const float* W0   = (const float*)d_in[3];
    const float* b0   = (const float*)d_in[4];
    const float* W1a  = (const float*)d_in[5];
    const float* b1a  = (const float*)d_in[6];
    const float* W1b  = (const float*)d_in[7];
    const float* b1b  = (const float*)d_in[8];
    const float* Wrel1  = (const float*)d_in[9];
    const float* brel1  = (const float*)d_in[10];
    const float* Wroot1 = (const float*)d_in[11];
    const float* W2a  = (const float*)d_in[12];
    const float* b2a  = (const float*)d_in[13];
    const float* W2b  = (const float*)d_in[14];
    const float* b2b  = (const float*)d_in[15];
    const float* Wrel2  = (const float*)d_in[16];
    const float* brel2  = (const float*)d_in[17];
    const float* Wroot2 = (const float*)d_in[18];
    const float* Wg   = (const float*)d_in[19];
    const float* bg   = (const float*)d_in[20];
    const float* Wr1  = (const float*)d_in[21];
    const float* br1  = (const float*)d_in[22];
    const float* gg1  = (const float*)d_in[23];
    const float* be1  = (const float*)d_in[24];
    const float* Wr2  = (const float*)d_in[25];
    const float* br2  = (const float*)d_in[26];
    const float* gg2  = (const float*)d_in[27];
    const float* be2  = (const float*)d_in[28];
    const float* Wout = (const float*)d_in[29];

    float *bufA, *bufB, *bufC, *scores, *skey, *o1, *o2;
    int *iota, *sidx, *newid, *src2, *dst2, *offs;
    int *keys, *keysB, *vals, *valsB, *counts, *rowptr;
    unsigned char *mask2, *cubtmp;
    cudaGetSymbolAddress((void**)&bufA, g_bufA);
    cudaGetSymbolAddress((void**)&bufB, g_bufB);
    cudaGetSymbolAddress((void**)&bufC, g_bufC);
    cudaGetSymbolAddress((void**)&scores, g_scores);
    cudaGetSymbolAddress((void**)&skey, g_skey);
    cudaGetSymbolAddress((void**)&iota, g_iota);
    cudaGetSymbolAddress((void**)&sidx, g_sidx);
    cudaGetSymbolAddress((void**)&newid, g_newid);
    cudaGetSymbolAddress((void**)&src2, g_src2);
    cudaGetSymbolAddress((void**)&dst2, g_dst2);
    cudaGetSymbolAddress((void**)&mask2, g_mask2);
    cudaGetSymbolAddress((void**)&offs, g_offs);
    cudaGetSymbolAddress((void**)&o1, g_out1);
    cudaGetSymbolAddress((void**)&o2, g_out2);
    cudaGetSymbolAddress((void**)&keys, g_keys);
    cudaGetSymbolAddress((void**)&keysB, g_keysB);
    cudaGetSymbolAddress((void**)&vals, g_vals);
    cudaGetSymbolAddress((void**)&valsB, g_valsB);
    cudaGetSymbolAddress((void**)&counts, g_counts);
    cudaGetSymbolAddress((void**)&rowptr, g_rowptr);
    cudaGetSymbolAddress((void**)&cubtmp, g_cubtmp);

    // ---- layer-1 CSR (all edges valid), deterministic edge order
    build_csr(dst, src, nullptr, keys, keysB, vals, valsB, counts, rowptr, cubtmp, NB_);

    // ---- stage 0: h0 = relu(x @ W0 + b0) -> bufA
    gemm_kernel<FF_, true><<<NB_ / 64, 256>>>(x, W0, b0, bufA);

    // ---- GIN layer 1: t = h0 + segsum(h0[src] -> dst) ; h1 = nn(t)
    agg_kernel<true><<<NB_ / 8, 256>>>(bufA, rowptr, valsB, bufB, NB_);
    gemm_kernel<CC_, true ><<<NB_ / 64, 256>>>(bufB, W1a, b1a, bufC);
    gemm_kernel<CC_, false><<<NB_ / 64, 256>>>(bufC, W1b, b1b, bufB);  // h1 = bufB

    // ---- SAGPool 1
    agg_kernel<false><<<NB_ / 8, 256>>>(bufB, rowptr, valsB, bufA, NB_);
    score_kernel<<<(NB_ + 255) / 256, 256>>>(bufA, bufB, Wrel1, brel1, Wroot1, scores, NB_);
    iota_kernel<<<(NB_ + 255) / 256, 256>>>(iota, NB_);
    offs_kernel<<<1, 32>>>(offs, NPG_);
    {
        size_t tmp = 0;
        cub::DeviceSegmentedRadixSort::SortPairsDescending(
            nullptr, tmp, scores, skey, iota, sidx, NB_, BGR_, offs, offs + 1);
        if (tmp > sizeof(g_cubtmp)) tmp = sizeof(g_cubtmp);
        cub::DeviceSegmentedRadixSort::SortPairsDescending(
            (void*)cubtmp, tmp, scores, skey, iota, sidx, NB_, BGR_, offs, offs + 1);
    }
    filln1_kernel<<<(NB_ + 255) / 256, 256>>>(newid, NB_);
    select_kernel<<<NB1_ / 8, 256>>>(skey, sidx, bufB, bufC, newid, NPG_, KK1_);  // h2 = bufC
    mean_kernel<<<BGR_, 256>>>(bufC, o1, KK1_);
    remap_kernel<<<EDG_ / 256, 256>>>(src, dst, newid, src2, dst2, mask2);

    // ---- layer-2 CSR (masked edges excluded), deterministic edge order
    build_csr(dst2, src2, mask2, keys, keysB, vals, valsB, counts, rowptr, cubtmp, NB1_);

    // ---- GIN layer 2
    agg_kernel<true><<<NB1_ / 8, 256>>>(bufC, rowptr, valsB, bufA, NB1_);
    gemm_kernel<CC_, true ><<<NB1_ / 64, 256>>>(bufA, W2a, b2a, bufB);
    gemm_kernel<CC_, false><<<NB1_ / 64, 256>>>(bufB, W2b, b2b, bufC);  // h3 = bufC

    // ---- SAGPool 2
    agg_kernel<false><<<NB1_ / 8, 256>>>(bufC, rowptr, valsB, bufA, NB1_);
    score_kernel<<<(NB1_ + 255) / 256, 256>>>(bufA, bufC, Wrel2, brel2, Wroot2, scores, NB1_);
    iota_kernel<<<(NB1_ + 255) / 256, 256>>>(iota, NB1_);
    offs_kernel<<<1, 32>>>(offs, KK1_);
    {
        size_t tmp = 0;
        cub::DeviceSegmentedRadixSort::SortPairsDescending(
            nullptr, tmp, scores, skey, iota, sidx, NB1_, BGR_, offs, offs + 1);
        if (tmp > sizeof(g_cubtmp)) tmp = sizeof(g_cubtmp);
        cub::DeviceSegmentedRadixSort::SortPairsDescending(
            (void*)cubtmp, tmp, scores, skey, iota, sidx, NB1_, BGR_, offs, offs + 1);
    }
    select_kernel<<<NB2_ / 8, 256>>>(skey, sidx, bufC, bufB, newid, KK1_, KK2_);  // h4 = bufB
    mean_kernel<<<BGR_, 256>>>(bufB, o2, KK2_);

    // ---- head
    head_kernel<<<1, 256>>>(o1, o2, Wg, bg, Wr1, br1, gg1, be1,
                            Wr2, br2, gg2, be2, Wout, (float*)d_out);
}